// round 2
// baseline (speedup 1.0000x reference)
#include <cuda_runtime.h>
#include <math.h>

#define SEQ 2048
#define DM 1024
#define DFF 4096
#define NH 16
#define DKH 64
#define LN_EPS 1e-6f

// ---------------- scratch (allocation-free: device globals) ----------------
__device__ float g_normx[SEQ * DM];
__device__ float g_h[SEQ * DM];
__device__ float g_q[SEQ * DM];
__device__ float g_k[SEQ * DM];
__device__ float g_v[SEQ * DM];
__device__ float g_ctx[SEQ * DM];
__device__ float g_mha[SEQ * DM];
__device__ float g_part1[SEQ * DM];
__device__ float g_norm2[SEQ * DM];
__device__ float g_ffh[(size_t)SEQ * DFF];

// ---------------- LayerNorm: y = g * (x - mean)/(std + eps) + b ------------
__global__ void ln_kernel(const float* __restrict__ x, const float* __restrict__ g,
                          const float* __restrict__ b, float* __restrict__ y) {
    int row = blockIdx.x;
    const float* xr = x + (size_t)row * DM;
    float* yr = y + (size_t)row * DM;
    __shared__ float red[256];
    int t = threadIdx.x;

    float s = 0.f;
    for (int c = t; c < DM; c += 256) s += xr[c];
    red[t] = s; __syncthreads();
    for (int st = 128; st > 0; st >>= 1) {
        if (t < st) red[t] += red[t + st];
        __syncthreads();
    }
    float mean = red[0] * (1.0f / DM);
    __syncthreads();

    float sq = 0.f;
    for (int c = t; c < DM; c += 256) { float d = xr[c] - mean; sq += d * d; }
    red[t] = sq; __syncthreads();
    for (int st = 128; st > 0; st >>= 1) {
        if (t < st) red[t] += red[t + st];
        __syncthreads();
    }
    float inv = 1.0f / (sqrtf(red[0] * (1.0f / DM)) + LN_EPS);

    for (int c = t; c < DM; c += 256)
        yr[c] = g[c] * ((xr[c] - mean) * inv) + b[c];
}

// ---------------- generic fp32 GEMM ----------------------------------------
// C[z][M,N] = scale * A[z][M,K] @ op(B[z]) + bias + resid, optional ReLU.
// TB==0: B is [K,N] row-major (NN).  TB==1: B is [N,K] row-major (NT).
template <int TB>
__global__ void __launch_bounds__(256, 2)
gemm_kernel(const float* __restrict__ A, int lda, long sA,
            const float* __restrict__ B, int ldb, long sB,
            const float* __restrict__ bias,
            const float* __restrict__ resid, int ldr, long sR,
            float* __restrict__ C, int ldc, long sC,
            int M, int N, int K, float scale, int relu) {
    __shared__ float As[16][128];
    __shared__ float Bs[16][128];
    int z = blockIdx.z;
    A += (long)z * sA;
    B += (long)z * sB;
    C += (long)z * sC;
    if (resid) resid += (long)z * sR;

    int row0 = blockIdx.y * 128;
    int col0 = blockIdx.x * 128;
    int tid = threadIdx.x;
    int tx = tid & 15;
    int ty = tid >> 4;

    float acc[8][8];
#pragma unroll
    for (int i = 0; i < 8; i++)
#pragma unroll
        for (int j = 0; j < 8; j++) acc[i][j] = 0.f;

    for (int k0 = 0; k0 < K; k0 += 16) {
        // load A tile (128 rows x 16 k), transposed into As[k][row]
        for (int i = tid; i < 128 * 16; i += 256) {
            int r = i >> 4, c = i & 15;
            int row = row0 + r;
            As[c][r] = (row < M) ? A[(long)row * lda + k0 + c] : 0.f;
        }
        if (TB == 0) {
            for (int i = tid; i < 16 * 128; i += 256) {
                int r = i >> 7, c = i & 127;
                int col = col0 + c;
                Bs[r][c] = (col < N) ? B[(long)(k0 + r) * ldb + col] : 0.f;
            }
        } else {
            for (int i = tid; i < 128 * 16; i += 256) {
                int r = i >> 4, c = i & 15;
                int col = col0 + r;
                Bs[c][r] = (col < N) ? B[(long)col * ldb + k0 + c] : 0.f;
            }
        }
        __syncthreads();

#pragma unroll
        for (int kk = 0; kk < 16; kk++) {
            float4 a0 = *(const float4*)&As[kk][ty * 8];
            float4 a1 = *(const float4*)&As[kk][ty * 8 + 4];
            float4 b0 = *(const float4*)&Bs[kk][tx * 8];
            float4 b1 = *(const float4*)&Bs[kk][tx * 8 + 4];
            float av[8] = {a0.x, a0.y, a0.z, a0.w, a1.x, a1.y, a1.z, a1.w};
            float bv[8] = {b0.x, b0.y, b0.z, b0.w, b1.x, b1.y, b1.z, b1.w};
#pragma unroll
            for (int i = 0; i < 8; i++)
#pragma unroll
                for (int j = 0; j < 8; j++) acc[i][j] += av[i] * bv[j];
        }
        __syncthreads();
    }

#pragma unroll
    for (int i = 0; i < 8; i++) {
        int row = row0 + ty * 8 + i;
        if (row >= M) continue;
#pragma unroll
        for (int j = 0; j < 8; j++) {
            int col = col0 + tx * 8 + j;
            if (col >= N) continue;
            float v = acc[i][j] * scale;
            if (bias) v += bias[col];
            if (resid) v += resid[(long)row * ldr + col];
            if (relu) v = fmaxf(v, 0.f);
            C[(long)row * ldc + col] = v;
        }
    }
}

// ---------------- causal softmax, in place on [NH, SEQ, SEQ] ----------------
__global__ void softmax_kernel(float* __restrict__ attn) {
    int h = blockIdx.y;
    int i = blockIdx.x;
    float* row = attn + ((size_t)h * SEQ + i) * SEQ;
    int len = i + 1;
    __shared__ float red[256];
    int t = threadIdx.x;

    float m = -3.4e38f;
    for (int j = t; j < len; j += 256) m = fmaxf(m, row[j]);
    red[t] = m; __syncthreads();
    for (int st = 128; st > 0; st >>= 1) {
        if (t < st) red[t] = fmaxf(red[t], red[t + st]);
        __syncthreads();
    }
    m = red[0];
    __syncthreads();

    float s = 0.f;
    for (int j = t; j < len; j += 256) {
        float e = expf(row[j] - m);
        row[j] = e;
        s += e;
    }
    red[t] = s; __syncthreads();
    for (int st = 128; st > 0; st >>= 1) {
        if (t < st) red[t] += red[t + st];
        __syncthreads();
    }
    float inv = 1.0f / red[0];

    for (int j = t; j < len; j += 256) row[j] *= inv;
    for (int j = len + t; j < SEQ; j += 256) row[j] = 0.f;  // mask region (d_out is poisoned)
}

// ---------------- launcher --------------------------------------------------
extern "C" void kernel_launch(void* const* d_in, const int* in_sizes, int n_in,
                              void* d_out, int out_size) {
    (void)in_sizes; (void)n_in; (void)out_size;
    const float* x     = (const float*)d_in[0];
    const float* g1    = (const float*)d_in[1];
    const float* beta1 = (const float*)d_in[2];
    const float* W_in  = (const float*)d_in[3];
    const float* b_in  = (const float*)d_in[4];
    const float* Wq    = (const float*)d_in[5];
    const float* bq    = (const float*)d_in[6];
    const float* Wk    = (const float*)d_in[7];
    const float* bk    = (const float*)d_in[8];
    const float* Wv    = (const float*)d_in[9];
    const float* bv    = (const float*)d_in[10];
    const float* Wo    = (const float*)d_in[11];
    const float* bo    = (const float*)d_in[12];
    const float* W2    = (const float*)d_in[13];
    const float* b2    = (const float*)d_in[14];
    const float* g2    = (const float*)d_in[15];
    const float* beta2 = (const float*)d_in[16];
    const float* Wf1   = (const float*)d_in[17];
    const float* bf1   = (const float*)d_in[18];
    const float* Wf2   = (const float*)d_in[19];
    const float* bf2   = (const float*)d_in[20];

    float* out = (float*)d_out;                   // [SEQ, DM]
    float* attn = out + (size_t)SEQ * DM;         // [NH, SEQ, SEQ]

    float *p_normx, *p_h, *p_q, *p_k, *p_v, *p_ctx, *p_mha, *p_part1, *p_norm2, *p_ffh;
    cudaGetSymbolAddress((void**)&p_normx, g_normx);
    cudaGetSymbolAddress((void**)&p_h, g_h);
    cudaGetSymbolAddress((void**)&p_q, g_q);
    cudaGetSymbolAddress((void**)&p_k, g_k);
    cudaGetSymbolAddress((void**)&p_v, g_v);
    cudaGetSymbolAddress((void**)&p_ctx, g_ctx);
    cudaGetSymbolAddress((void**)&p_mha, g_mha);
    cudaGetSymbolAddress((void**)&p_part1, g_part1);
    cudaGetSymbolAddress((void**)&p_norm2, g_norm2);
    cudaGetSymbolAddress((void**)&p_ffh, g_ffh);

    dim3 blk(256);
    auto grd = [](int M, int N, int Z) { return dim3((N + 127) / 128, (M + 127) / 128, Z); };

    // 1) norm_x = LN(x)
    ln_kernel<<<SEQ, 256>>>(x, g1, beta1, p_normx);

    // 2) h = norm_x @ W_in + b_in
    gemm_kernel<0><<<grd(SEQ, DM, 1), blk>>>(p_normx, DM, 0, W_in, DM, 0, b_in,
                                             nullptr, 0, 0, p_h, DM, 0,
                                             SEQ, DM, DM, 1.f, 0);
    // 3) q,k,v
    gemm_kernel<0><<<grd(SEQ, DM, 1), blk>>>(p_h, DM, 0, Wq, DM, 0, bq,
                                             nullptr, 0, 0, p_q, DM, 0,
                                             SEQ, DM, DM, 1.f, 0);
    gemm_kernel<0><<<grd(SEQ, DM, 1), blk>>>(p_h, DM, 0, Wk, DM, 0, bk,
                                             nullptr, 0, 0, p_k, DM, 0,
                                             SEQ, DM, DM, 1.f, 0);
    gemm_kernel<0><<<grd(SEQ, DM, 1), blk>>>(p_h, DM, 0, Wv, DM, 0, bv,
                                             nullptr, 0, 0, p_v, DM, 0,
                                             SEQ, DM, DM, 1.f, 0);

    // 4) scores = q @ k^T / sqrt(dk)  per head, into d_out attn region
    gemm_kernel<1><<<grd(SEQ, SEQ, NH), blk>>>(p_q, DM, DKH, p_k, DM, DKH, nullptr,
                                               nullptr, 0, 0, attn, SEQ, (long)SEQ * SEQ,
                                               SEQ, SEQ, DKH, 0.125f, 0);
    // 5) causal softmax in place
    softmax_kernel<<<dim3(SEQ, NH), 256>>>(attn);

    // 6) ctx = attn @ v   (per head, N = 64)
    gemm_kernel<0><<<grd(SEQ, DKH, NH), blk>>>(attn, SEQ, (long)SEQ * SEQ, p_v, DM, DKH,
                                               nullptr, nullptr, 0, 0, p_ctx, DM, DKH,
                                               SEQ, DKH, SEQ, 1.f, 0);

    // 7) mha = ctx @ Wo + bo
    gemm_kernel<0><<<grd(SEQ, DM, 1), blk>>>(p_ctx, DM, 0, Wo, DM, 0, bo,
                                             nullptr, 0, 0, p_mha, DM, 0,
                                             SEQ, DM, DM, 1.f, 0);
    // 8) part1 = x + mha @ W2 + b2
    gemm_kernel<0><<<grd(SEQ, DM, 1), blk>>>(p_mha, DM, 0, W2, DM, 0, b2,
                                             x, DM, 0, p_part1, DM, 0,
                                             SEQ, DM, DM, 1.f, 0);
    // 9) norm2 = LN(part1)
    ln_kernel<<<SEQ, 256>>>(p_part1, g2, beta2, p_norm2);

    // 10) ffh = relu(norm2 @ Wf1 + bf1)
    gemm_kernel<0><<<grd(SEQ, DFF, 1), blk>>>(p_norm2, DM, 0, Wf1, DFF, 0, bf1,
                                              nullptr, 0, 0, p_ffh, DFF, 0,
                                              SEQ, DFF, DM, 1.f, 1);
    // 11) out = norm2 + ffh @ Wf2 + bf2
    gemm_kernel<0><<<grd(SEQ, DM, 1), blk>>>(p_ffh, DFF, 0, Wf2, DM, 0, bf2,
                                             p_norm2, DM, 0, out, DM, 0,
                                             SEQ, DM, DFF, 1.f, 0);
}

// round 3
// speedup vs baseline: 3.6282x; 3.6282x over previous
#include <cuda_runtime.h>
#include <math.h>
#include <stdint.h>

#define SEQ 2048
#define DM 1024
#define DFF 4096
#define NH 16
#define DKH 64
#define LN_EPS 1e-6f
#define BK 16

// ---------------- scratch (allocation-free: device globals) ----------------
__device__ float g_normx[SEQ * DM];
__device__ float g_h[SEQ * DM];
__device__ float g_q[SEQ * DM];
__device__ float g_k[SEQ * DM];
__device__ float g_v[SEQ * DM];
__device__ float g_ctx[SEQ * DM];
__device__ float g_mha[SEQ * DM];
__device__ float g_part1[SEQ * DM];
__device__ float g_norm2[SEQ * DM];
__device__ float g_ffh[(size_t)SEQ * DFF];

// ---------------- helpers ---------------------------------------------------
__device__ __forceinline__ uint32_t f2tf32(float f) {
    uint32_t u;
    asm("cvt.rna.tf32.f32 %0, %1;" : "=r"(u) : "f"(f));
    return u;
}

__device__ __forceinline__ void mma_tf32(float* c, const uint32_t* a, const uint32_t* b) {
    asm volatile(
        "mma.sync.aligned.m16n8k8.row.col.f32.tf32.tf32.f32 "
        "{%0,%1,%2,%3}, {%4,%5,%6,%7}, {%8,%9}, {%0,%1,%2,%3};\n"
        : "+f"(c[0]), "+f"(c[1]), "+f"(c[2]), "+f"(c[3])
        : "r"(a[0]), "r"(a[1]), "r"(a[2]), "r"(a[3]), "r"(b[0]), "r"(b[1]));
}

// ---------------- LayerNorm -------------------------------------------------
__global__ void ln_kernel(const float* __restrict__ x, const float* __restrict__ g,
                          const float* __restrict__ b, float* __restrict__ y) {
    int row = blockIdx.x;
    const float* xr = x + (size_t)row * DM;
    float* yr = y + (size_t)row * DM;
    __shared__ float red[256];
    int t = threadIdx.x;

    float s = 0.f;
    for (int c = t; c < DM; c += 256) s += xr[c];
    red[t] = s; __syncthreads();
    for (int st = 128; st > 0; st >>= 1) {
        if (t < st) red[t] += red[t + st];
        __syncthreads();
    }
    float mean = red[0] * (1.0f / DM);
    __syncthreads();

    float sq = 0.f;
    for (int c = t; c < DM; c += 256) { float d = xr[c] - mean; sq += d * d; }
    red[t] = sq; __syncthreads();
    for (int st = 128; st > 0; st >>= 1) {
        if (t < st) red[t] += red[t + st];
        __syncthreads();
    }
    float inv = 1.0f / (sqrtf(red[0] * (1.0f / DM)) + LN_EPS);

    for (int c = t; c < DM; c += 256)
        yr[c] = g[c] * ((xr[c] - mean) * inv) + b[c];
}

// ---------------- tf32 tensor-core GEMM -------------------------------------
// C[z][M,N] = scale * A[z][M,K] @ op(B[z]) + bias + resid, optional ReLU.
// TB==0: B is [K,N] row-major.  TB==1: B is [N,K] row-major.
// Requires: M % BM == 0, N % BN == 0, K % BK == 0.
template <int BM, int BN, int TB>
__global__ void __launch_bounds__(256, 2)
mma_gemm(const float* __restrict__ A, int lda, long sA,
         const float* __restrict__ B, int ldb, long sB,
         const float* __restrict__ bias,
         const float* __restrict__ resid, int ldr, long sR,
         float* __restrict__ C, int ldc, long sC,
         int M, int N, int K, float scale, int relu) {
    constexpr int WN_CT = (BN >= 128) ? 4 : 2;  // warps along N
    constexpr int WM_CT = 8 / WN_CT;            // warps along M
    constexpr int WM = BM / WM_CT;              // 64 or 32
    constexpr int WN = BN / WN_CT;              // 32
    constexpr int MI = WM / 16;
    constexpr int NI = WN / 8;
    constexpr int AV = BM * BK / (4 * 256);     // float4 per thread (A tile)
    constexpr int BV = BN * BK / (4 * 256);     // float4 per thread (B tile)

    __shared__ uint32_t As[BK][BM + 8];
    __shared__ uint32_t Bs[BK][BN + 8];

    int z = blockIdx.z;
    A += (long)z * sA;
    B += (long)z * sB;
    C += (long)z * sC;
    if (resid) resid += (long)z * sR;

    const int row0 = blockIdx.y * BM;
    const int col0 = blockIdx.x * BN;
    const int tid = threadIdx.x;
    const int warp = tid >> 5, lane = tid & 31;
    const int gid = lane >> 2, tig = lane & 3;
    const int wm0 = (warp / WN_CT) * WM;
    const int wn0 = (warp % WN_CT) * WN;

    float acc[MI][NI][4];
#pragma unroll
    for (int mi = 0; mi < MI; mi++)
#pragma unroll
        for (int ni = 0; ni < NI; ni++)
#pragma unroll
            for (int r = 0; r < 4; r++) acc[mi][ni][r] = 0.f;

    float4 pa[AV], pb[BV];

    auto loadA = [&](int k0) {
#pragma unroll
        for (int i = 0; i < AV; i++) {
            int idx = tid + i * 256;
            int r = idx >> 2, c4 = idx & 3;  // BK/4 == 4
            pa[i] = *(const float4*)&A[(long)(row0 + r) * lda + k0 + c4 * 4];
        }
    };
    auto loadB = [&](int k0) {
#pragma unroll
        for (int i = 0; i < BV; i++) {
            int idx = tid + i * 256;
            if (TB == 0) {
                int c = idx / (BN / 4), v4 = idx % (BN / 4);
                pb[i] = *(const float4*)&B[(long)(k0 + c) * ldb + col0 + v4 * 4];
            } else {
                int col = idx >> 2, c4 = idx & 3;
                pb[i] = *(const float4*)&B[(long)(col0 + col) * ldb + k0 + c4 * 4];
            }
        }
    };
    auto storeTiles = [&]() {
#pragma unroll
        for (int i = 0; i < AV; i++) {
            int idx = tid + i * 256;
            int r = idx >> 2, c4 = idx & 3;
            const float* f = &pa[i].x;
#pragma unroll
            for (int j = 0; j < 4; j++) As[c4 * 4 + j][r] = f2tf32(f[j]);
        }
#pragma unroll
        for (int i = 0; i < BV; i++) {
            int idx = tid + i * 256;
            const float* f = &pb[i].x;
            if (TB == 0) {
                int c = idx / (BN / 4), v4 = idx % (BN / 4);
                uint4 u;
                u.x = f2tf32(f[0]); u.y = f2tf32(f[1]);
                u.z = f2tf32(f[2]); u.w = f2tf32(f[3]);
                *(uint4*)&Bs[c][v4 * 4] = u;
            } else {
                int col = idx >> 2, c4 = idx & 3;
#pragma unroll
                for (int j = 0; j < 4; j++) Bs[c4 * 4 + j][col] = f2tf32(f[j]);
            }
        }
    };

    loadA(0);
    loadB(0);
    storeTiles();
    __syncthreads();

    for (int k0 = 0; k0 < K; k0 += BK) {
        bool has_next = (k0 + BK) < K;
        if (has_next) { loadA(k0 + BK); loadB(k0 + BK); }

#pragma unroll
        for (int ks = 0; ks < BK / 8; ks++) {
            const int kk = ks * 8;
            uint32_t af[MI][4], bf[NI][2];
#pragma unroll
            for (int mi = 0; mi < MI; mi++) {
                int r = wm0 + mi * 16 + gid;
                af[mi][0] = As[kk + tig][r];
                af[mi][1] = As[kk + tig][r + 8];
                af[mi][2] = As[kk + tig + 4][r];
                af[mi][3] = As[kk + tig + 4][r + 8];
            }
#pragma unroll
            for (int ni = 0; ni < NI; ni++) {
                int cc = wn0 + ni * 8 + gid;
                bf[ni][0] = Bs[kk + tig][cc];
                bf[ni][1] = Bs[kk + tig + 4][cc];
            }
#pragma unroll
            for (int mi = 0; mi < MI; mi++)
#pragma unroll
                for (int ni = 0; ni < NI; ni++)
                    mma_tf32(acc[mi][ni], af[mi], bf[ni]);
        }
        __syncthreads();
        if (has_next) {
            storeTiles();
        }
        __syncthreads();
    }

    // epilogue
#pragma unroll
    for (int mi = 0; mi < MI; mi++) {
        int r_lo = row0 + wm0 + mi * 16 + gid;
#pragma unroll
        for (int ni = 0; ni < NI; ni++) {
            int c_ = col0 + wn0 + ni * 8 + tig * 2;
            float b0 = 0.f, b1 = 0.f;
            if (bias) { b0 = bias[c_]; b1 = bias[c_ + 1]; }
#pragma unroll
            for (int half = 0; half < 2; half++) {
                int r_ = r_lo + half * 8;
                float v0 = acc[mi][ni][half * 2 + 0] * scale + b0;
                float v1 = acc[mi][ni][half * 2 + 1] * scale + b1;
                if (resid) {
                    v0 += resid[(long)r_ * ldr + c_];
                    v1 += resid[(long)r_ * ldr + c_ + 1];
                }
                if (relu) { v0 = fmaxf(v0, 0.f); v1 = fmaxf(v1, 0.f); }
                float2 o = make_float2(v0, v1);
                *(float2*)&C[(long)r_ * ldc + c_] = o;
            }
        }
    }
}

// ---------------- causal softmax, in place on [NH, SEQ, SEQ] ----------------
__global__ void softmax_kernel(float* __restrict__ attn) {
    int h = blockIdx.y;
    int i = blockIdx.x;
    float* row = attn + ((size_t)h * SEQ + i) * SEQ;
    int len = i + 1;
    __shared__ float red[256];
    int t = threadIdx.x;

    float m = -3.4e38f;
    for (int j = t; j < len; j += 256) m = fmaxf(m, row[j]);
    red[t] = m; __syncthreads();
    for (int st = 128; st > 0; st >>= 1) {
        if (t < st) red[t] = fmaxf(red[t], red[t + st]);
        __syncthreads();
    }
    m = red[0];
    __syncthreads();

    float s = 0.f;
    for (int j = t; j < len; j += 256) {
        float e = expf(row[j] - m);
        row[j] = e;
        s += e;
    }
    red[t] = s; __syncthreads();
    for (int st = 128; st > 0; st >>= 1) {
        if (t < st) red[t] += red[t + st];
        __syncthreads();
    }
    float inv = 1.0f / red[0];

    for (int j = t; j < len; j += 256) row[j] *= inv;
    for (int j = len + t; j < SEQ; j += 256) row[j] = 0.f;  // causal mask region
}

// ---------------- launcher --------------------------------------------------
extern "C" void kernel_launch(void* const* d_in, const int* in_sizes, int n_in,
                              void* d_out, int out_size) {
    (void)in_sizes; (void)n_in; (void)out_size;
    const float* x     = (const float*)d_in[0];
    const float* g1    = (const float*)d_in[1];
    const float* beta1 = (const float*)d_in[2];
    const float* W_in  = (const float*)d_in[3];
    const float* b_in  = (const float*)d_in[4];
    const float* Wq    = (const float*)d_in[5];
    const float* bq    = (const float*)d_in[6];
    const float* Wk    = (const float*)d_in[7];
    const float* bk    = (const float*)d_in[8];
    const float* Wv    = (const float*)d_in[9];
    const float* bv    = (const float*)d_in[10];
    const float* Wo    = (const float*)d_in[11];
    const float* bo    = (const float*)d_in[12];
    const float* W2    = (const float*)d_in[13];
    const float* b2    = (const float*)d_in[14];
    const float* g2    = (const float*)d_in[15];
    const float* beta2 = (const float*)d_in[16];
    const float* Wf1   = (const float*)d_in[17];
    const float* bf1   = (const float*)d_in[18];
    const float* Wf2   = (const float*)d_in[19];
    const float* bf2   = (const float*)d_in[20];

    float* out = (float*)d_out;            // [SEQ, DM]
    float* attn = out + (size_t)SEQ * DM;  // [NH, SEQ, SEQ]

    float *p_normx, *p_h, *p_q, *p_k, *p_v, *p_ctx, *p_mha, *p_part1, *p_norm2, *p_ffh;
    cudaGetSymbolAddress((void**)&p_normx, g_normx);
    cudaGetSymbolAddress((void**)&p_h, g_h);
    cudaGetSymbolAddress((void**)&p_q, g_q);
    cudaGetSymbolAddress((void**)&p_k, g_k);
    cudaGetSymbolAddress((void**)&p_v, g_v);
    cudaGetSymbolAddress((void**)&p_ctx, g_ctx);
    cudaGetSymbolAddress((void**)&p_mha, g_mha);
    cudaGetSymbolAddress((void**)&p_part1, g_part1);
    cudaGetSymbolAddress((void**)&p_norm2, g_norm2);
    cudaGetSymbolAddress((void**)&p_ffh, g_ffh);

    dim3 blk(256);

    // 1) norm_x = LN(x)
    ln_kernel<<<SEQ, 256>>>(x, g1, beta1, p_normx);

    // 2) h = norm_x @ W_in + b_in
    mma_gemm<128, 128, 0><<<dim3(8, 16, 1), blk>>>(p_normx, DM, 0, W_in, DM, 0, b_in,
                                                   nullptr, 0, 0, p_h, DM, 0,
                                                   SEQ, DM, DM, 1.f, 0);
    // 3) q, k, v
    mma_gemm<128, 128, 0><<<dim3(8, 16, 1), blk>>>(p_h, DM, 0, Wq, DM, 0, bq,
                                                   nullptr, 0, 0, p_q, DM, 0,
                                                   SEQ, DM, DM, 1.f, 0);
    mma_gemm<128, 128, 0><<<dim3(8, 16, 1), blk>>>(p_h, DM, 0, Wk, DM, 0, bk,
                                                   nullptr, 0, 0, p_k, DM, 0,
                                                   SEQ, DM, DM, 1.f, 0);
    mma_gemm<128, 128, 0><<<dim3(8, 16, 1), blk>>>(p_h, DM, 0, Wv, DM, 0, bv,
                                                   nullptr, 0, 0, p_v, DM, 0,
                                                   SEQ, DM, DM, 1.f, 0);

    // 4) scores = q @ k^T / 8 per head -> attn region of d_out
    mma_gemm<128, 128, 1><<<dim3(16, 16, NH), blk>>>(p_q, DM, DKH, p_k, DM, DKH, nullptr,
                                                     nullptr, 0, 0, attn, SEQ, (long)SEQ * SEQ,
                                                     SEQ, SEQ, DKH, 0.125f, 0);
    // 5) causal softmax in place
    softmax_kernel<<<dim3(SEQ, NH), 256>>>(attn);

    // 6) ctx = attn @ v (per head)
    mma_gemm<128, 64, 0><<<dim3(1, 16, NH), blk>>>(attn, SEQ, (long)SEQ * SEQ, p_v, DM, DKH,
                                                   nullptr, nullptr, 0, 0, p_ctx, DM, DKH,
                                                   SEQ, DKH, SEQ, 1.f, 0);

    // 7) mha = ctx @ Wo + bo
    mma_gemm<128, 128, 0><<<dim3(8, 16, 1), blk>>>(p_ctx, DM, 0, Wo, DM, 0, bo,
                                                   nullptr, 0, 0, p_mha, DM, 0,
                                                   SEQ, DM, DM, 1.f, 0);
    // 8) part1 = x + mha @ W2 + b2
    mma_gemm<128, 128, 0><<<dim3(8, 16, 1), blk>>>(p_mha, DM, 0, W2, DM, 0, b2,
                                                   x, DM, 0, p_part1, DM, 0,
                                                   SEQ, DM, DM, 1.f, 0);
    // 9) norm2 = LN(part1)
    ln_kernel<<<SEQ, 256>>>(p_part1, g2, beta2, p_norm2);

    // 10) ffh = relu(norm2 @ Wf1 + bf1)
    mma_gemm<128, 128, 0><<<dim3(32, 16, 1), blk>>>(p_norm2, DM, 0, Wf1, DFF, 0, bf1,
                                                    nullptr, 0, 0, p_ffh, DFF, 0,
                                                    SEQ, DFF, DM, 1.f, 1);
    // 11) out = norm2 + ffh @ Wf2 + bf2
    mma_gemm<128, 128, 0><<<dim3(8, 16, 1), blk>>>(p_ffh, DFF, 0, Wf2, DM, 0, bf2,
                                                   p_norm2, DM, 0, out, DM, 0,
                                                   SEQ, DM, DFF, 1.f, 0);
}

// round 5
// speedup vs baseline: 3.6330x; 1.0013x over previous
#include <cuda_runtime.h>
#include <math.h>
#include <stdint.h>

#define SEQ 2048
#define DM 1024
#define DFF 4096
#define NH 16
#define DKH 64
#define LN_EPS 1e-6f
#define BK 16

// ---------------- scratch (allocation-free: device globals) ----------------
__device__ float g_normx[SEQ * DM];
__device__ float g_h[SEQ * DM];
__device__ float g_q[SEQ * DM];
__device__ float g_k[SEQ * DM];
__device__ float g_v[SEQ * DM];
__device__ float g_ctx[SEQ * DM];
__device__ float g_mha[SEQ * DM];
__device__ float g_part1[SEQ * DM];
__device__ float g_norm2[SEQ * DM];
__device__ float g_ffh[(size_t)SEQ * DFF];

// ---------------- helpers ---------------------------------------------------
__device__ __forceinline__ uint32_t f2tf32(float f) {
    uint32_t u;
    asm("cvt.rna.tf32.f32 %0, %1;" : "=r"(u) : "f"(f));
    return u;
}

__device__ __forceinline__ void mma_tf32(float* c, const uint32_t* a, const uint32_t* b) {
    asm volatile(
        "mma.sync.aligned.m16n8k8.row.col.f32.tf32.tf32.f32 "
        "{%0,%1,%2,%3}, {%4,%5,%6,%7}, {%8,%9}, {%0,%1,%2,%3};\n"
        : "+f"(c[0]), "+f"(c[1]), "+f"(c[2]), "+f"(c[3])
        : "r"(a[0]), "r"(a[1]), "r"(a[2]), "r"(a[3]), "r"(b[0]), "r"(b[1]));
}

// ---------------- LayerNorm -------------------------------------------------
__global__ void ln_kernel(const float* __restrict__ x, const float* __restrict__ g,
                          const float* __restrict__ b, float* __restrict__ y) {
    int row = blockIdx.x;
    const float* xr = x + (size_t)row * DM;
    float* yr = y + (size_t)row * DM;
    __shared__ float red[256];
    int t = threadIdx.x;

    float s = 0.f;
    for (int c = t; c < DM; c += 256) s += xr[c];
    red[t] = s; __syncthreads();
    for (int st = 128; st > 0; st >>= 1) {
        if (t < st) red[t] += red[t + st];
        __syncthreads();
    }
    float mean = red[0] * (1.0f / DM);
    __syncthreads();

    float sq = 0.f;
    for (int c = t; c < DM; c += 256) { float d = xr[c] - mean; sq += d * d; }
    red[t] = sq; __syncthreads();
    for (int st = 128; st > 0; st >>= 1) {
        if (t < st) red[t] += red[t + st];
        __syncthreads();
    }
    float inv = 1.0f / (sqrtf(red[0] * (1.0f / DM)) + LN_EPS);

    for (int c = t; c < DM; c += 256)
        yr[c] = g[c] * ((xr[c] - mean) * inv) + b[c];
}

// ---------------- tf32 tensor-core GEMM -------------------------------------
// C[z][M,N] = scale * A[z][M,K] @ op(B[z]) + bias + resid, optional ReLU.
// TB==0: B is [K,N] row-major.  TB==1: B is [N,K] row-major.
// Requires: M % BM == 0, N % BN == 0, K % BK == 0.
template <int BM, int BN, int TB>
__global__ void __launch_bounds__(256, 2)
mma_gemm(const float* __restrict__ A, int lda, long sA,
         const float* __restrict__ B, int ldb, long sB,
         const float* __restrict__ bias,
         const float* __restrict__ resid, int ldr, long sR,
         float* __restrict__ C, int ldc, long sC,
         int M, int N, int K, float scale, int relu) {
    constexpr int WN_CT = (BN >= 128) ? 4 : 2;  // warps along N
    constexpr int WM_CT = 8 / WN_CT;            // warps along M
    constexpr int WM = BM / WM_CT;              // 64 or 32
    constexpr int WN = BN / WN_CT;              // 32
    constexpr int MI = WM / 16;
    constexpr int NI = WN / 8;
    constexpr int AV = BM * BK / (4 * 256);     // float4 per thread (A tile)
    constexpr int BV = BN * BK / (4 * 256);     // float4 per thread (B tile)

    __shared__ uint32_t As[BK][BM + 8];
    __shared__ uint32_t Bs[BK][BN + 8];

    int z = blockIdx.z;
    A += (long)z * sA;
    B += (long)z * sB;
    C += (long)z * sC;
    if (resid) resid += (long)z * sR;

    const int row0 = blockIdx.y * BM;
    const int col0 = blockIdx.x * BN;
    const int tid = threadIdx.x;
    const int warp = tid >> 5, lane = tid & 31;
    const int gid = lane >> 2, tig = lane & 3;
    const int wm0 = (warp / WN_CT) * WM;
    const int wn0 = (warp % WN_CT) * WN;

    float acc[MI][NI][4];
#pragma unroll
    for (int mi = 0; mi < MI; mi++)
#pragma unroll
        for (int ni = 0; ni < NI; ni++)
#pragma unroll
            for (int r = 0; r < 4; r++) acc[mi][ni][r] = 0.f;

    float4 pa[AV], pb[BV];

    auto loadA = [&](int k0) {
#pragma unroll
        for (int i = 0; i < AV; i++) {
            int idx = tid + i * 256;
            int r = idx >> 2, c4 = idx & 3;  // BK/4 == 4
            pa[i] = *(const float4*)&A[(long)(row0 + r) * lda + k0 + c4 * 4];
        }
    };
    auto loadB = [&](int k0) {
#pragma unroll
        for (int i = 0; i < BV; i++) {
            int idx = tid + i * 256;
            if (TB == 0) {
                int c = idx / (BN / 4), v4 = idx % (BN / 4);
                pb[i] = *(const float4*)&B[(long)(k0 + c) * ldb + col0 + v4 * 4];
            } else {
                int col = idx >> 2, c4 = idx & 3;
                pb[i] = *(const float4*)&B[(long)(col0 + col) * ldb + k0 + c4 * 4];
            }
        }
    };
    auto storeTiles = [&]() {
#pragma unroll
        for (int i = 0; i < AV; i++) {
            int idx = tid + i * 256;
            int r = idx >> 2, c4 = idx & 3;
            const float* f = &pa[i].x;
#pragma unroll
            for (int j = 0; j < 4; j++) As[c4 * 4 + j][r] = f2tf32(f[j]);
        }
#pragma unroll
        for (int i = 0; i < BV; i++) {
            int idx = tid + i * 256;
            const float* f = &pb[i].x;
            if (TB == 0) {
                int c = idx / (BN / 4), v4 = idx % (BN / 4);
                uint4 u;
                u.x = f2tf32(f[0]); u.y = f2tf32(f[1]);
                u.z = f2tf32(f[2]); u.w = f2tf32(f[3]);
                *(uint4*)&Bs[c][v4 * 4] = u;
            } else {
                int col = idx >> 2, c4 = idx & 3;
#pragma unroll
                for (int j = 0; j < 4; j++) Bs[c4 * 4 + j][col] = f2tf32(f[j]);
            }
        }
    };

    loadA(0);
    loadB(0);
    storeTiles();
    __syncthreads();

    for (int k0 = 0; k0 < K; k0 += BK) {
        bool has_next = (k0 + BK) < K;
        if (has_next) { loadA(k0 + BK); loadB(k0 + BK); }

#pragma unroll
        for (int ks = 0; ks < BK / 8; ks++) {
            const int kk = ks * 8;
            uint32_t af[MI][4], bf[NI][2];
#pragma unroll
            for (int mi = 0; mi < MI; mi++) {
                int r = wm0 + mi * 16 + gid;
                af[mi][0] = As[kk + tig][r];
                af[mi][1] = As[kk + tig][r + 8];
                af[mi][2] = As[kk + tig + 4][r];
                af[mi][3] = As[kk + tig + 4][r + 8];
            }
#pragma unroll
            for (int ni = 0; ni < NI; ni++) {
                int cc = wn0 + ni * 8 + gid;
                bf[ni][0] = Bs[kk + tig][cc];
                bf[ni][1] = Bs[kk + tig + 4][cc];
            }
#pragma unroll
            for (int mi = 0; mi < MI; mi++)
#pragma unroll
                for (int ni = 0; ni < NI; ni++)
                    mma_tf32(acc[mi][ni], af[mi], bf[ni]);
        }
        __syncthreads();
        if (has_next) {
            storeTiles();
        }
        __syncthreads();
    }

    // epilogue
#pragma unroll
    for (int mi = 0; mi < MI; mi++) {
        int r_lo = row0 + wm0 + mi * 16 + gid;
#pragma unroll
        for (int ni = 0; ni < NI; ni++) {
            int c_ = col0 + wn0 + ni * 8 + tig * 2;
            float b0 = 0.f, b1 = 0.f;
            if (bias) { b0 = bias[c_]; b1 = bias[c_ + 1]; }
#pragma unroll
            for (int half = 0; half < 2; half++) {
                int r_ = r_lo + half * 8;
                float v0 = acc[mi][ni][half * 2 + 0] * scale + b0;
                float v1 = acc[mi][ni][half * 2 + 1] * scale + b1;
                if (resid) {
                    v0 += resid[(long)r_ * ldr + c_];
                    v1 += resid[(long)r_ * ldr + c_ + 1];
                }
                if (relu) { v0 = fmaxf(v0, 0.f); v1 = fmaxf(v1, 0.f); }
                float2 o = make_float2(v0, v1);
                *(float2*)&C[(long)r_ * ldc + c_] = o;
            }
        }
    }
}

// ---------------- causal softmax, in place on [NH, SEQ, SEQ] ----------------
__global__ void softmax_kernel(float* __restrict__ attn) {
    int h = blockIdx.y;
    int i = blockIdx.x;
    float* row = attn + ((size_t)h * SEQ + i) * SEQ;
    int len = i + 1;
    __shared__ float red[256];
    int t = threadIdx.x;

    float m = -3.4e38f;
    for (int j = t; j < len; j += 256) m = fmaxf(m, row[j]);
    red[t] = m; __syncthreads();
    for (int st = 128; st > 0; st >>= 1) {
        if (t < st) red[t] = fmaxf(red[t], red[t + st]);
        __syncthreads();
    }
    m = red[0];
    __syncthreads();

    float s = 0.f;
    for (int j = t; j < len; j += 256) {
        float e = expf(row[j] - m);
        row[j] = e;
        s += e;
    }
    red[t] = s; __syncthreads();
    for (int st = 128; st > 0; st >>= 1) {
        if (t < st) red[t] += red[t + st];
        __syncthreads();
    }
    float inv = 1.0f / red[0];

    for (int j = t; j < len; j += 256) row[j] *= inv;
    for (int j = len + t; j < SEQ; j += 256) row[j] = 0.f;  // causal mask region
}

// ---------------- launcher --------------------------------------------------
extern "C" void kernel_launch(void* const* d_in, const int* in_sizes, int n_in,
                              void* d_out, int out_size) {
    (void)in_sizes; (void)n_in; (void)out_size;
    const float* x     = (const float*)d_in[0];
    const float* g1    = (const float*)d_in[1];
    const float* beta1 = (const float*)d_in[2];
    const float* W_in  = (const float*)d_in[3];
    const float* b_in  = (const float*)d_in[4];
    const float* Wq    = (const float*)d_in[5];
    const float* bq    = (const float*)d_in[6];
    const float* Wk    = (const float*)d_in[7];
    const float* bk    = (const float*)d_in[8];
    const float* Wv    = (const float*)d_in[9];
    const float* bv    = (const float*)d_in[10];
    const float* Wo    = (const float*)d_in[11];
    const float* bo    = (const float*)d_in[12];
    const float* W2    = (const float*)d_in[13];
    const float* b2    = (const float*)d_in[14];
    const float* g2    = (const float*)d_in[15];
    const float* beta2 = (const float*)d_in[16];
    const float* Wf1   = (const float*)d_in[17];
    const float* bf1   = (const float*)d_in[18];
    const float* Wf2   = (const float*)d_in[19];
    const float* bf2   = (const float*)d_in[20];

    float* out = (float*)d_out;            // [SEQ, DM]
    float* attn = out + (size_t)SEQ * DM;  // [NH, SEQ, SEQ]

    float *p_normx, *p_h, *p_q, *p_k, *p_v, *p_ctx, *p_mha, *p_part1, *p_norm2, *p_ffh;
    cudaGetSymbolAddress((void**)&p_normx, g_normx);
    cudaGetSymbolAddress((void**)&p_h, g_h);
    cudaGetSymbolAddress((void**)&p_q, g_q);
    cudaGetSymbolAddress((void**)&p_k, g_k);
    cudaGetSymbolAddress((void**)&p_v, g_v);
    cudaGetSymbolAddress((void**)&p_ctx, g_ctx);
    cudaGetSymbolAddress((void**)&p_mha, g_mha);
    cudaGetSymbolAddress((void**)&p_part1, g_part1);
    cudaGetSymbolAddress((void**)&p_norm2, g_norm2);
    cudaGetSymbolAddress((void**)&p_ffh, g_ffh);

    dim3 blk(256);

    // 1) norm_x = LN(x)
    ln_kernel<<<SEQ, 256>>>(x, g1, beta1, p_normx);

    // 2) h = norm_x @ W_in + b_in
    mma_gemm<128, 128, 0><<<dim3(8, 16, 1), blk>>>(p_normx, DM, 0, W_in, DM, 0, b_in,
                                                   nullptr, 0, 0, p_h, DM, 0,
                                                   SEQ, DM, DM, 1.f, 0);
    // 3) q, k, v
    mma_gemm<128, 128, 0><<<dim3(8, 16, 1), blk>>>(p_h, DM, 0, Wq, DM, 0, bq,
                                                   nullptr, 0, 0, p_q, DM, 0,
                                                   SEQ, DM, DM, 1.f, 0);
    mma_gemm<128, 128, 0><<<dim3(8, 16, 1), blk>>>(p_h, DM, 0, Wk, DM, 0, bk,
                                                   nullptr, 0, 0, p_k, DM, 0,
                                                   SEQ, DM, DM, 1.f, 0);
    mma_gemm<128, 128, 0><<<dim3(8, 16, 1), blk>>>(p_h, DM, 0, Wv, DM, 0, bv,
                                                   nullptr, 0, 0, p_v, DM, 0,
                                                   SEQ, DM, DM, 1.f, 0);

    // 4) scores = q @ k^T / 8 per head -> attn region of d_out
    mma_gemm<128, 128, 1><<<dim3(16, 16, NH), blk>>>(p_q, DM, DKH, p_k, DM, DKH, nullptr,
                                                     nullptr, 0, 0, attn, SEQ, (long)SEQ * SEQ,
                                                     SEQ, SEQ, DKH, 0.125f, 0);
    // 5) causal softmax in place
    softmax_kernel<<<dim3(SEQ, NH), 256>>>(attn);

    // 6) ctx = attn @ v (per head)
    mma_gemm<128, 64, 0><<<dim3(1, 16, NH), blk>>>(attn, SEQ, (long)SEQ * SEQ, p_v, DM, DKH,
                                                   nullptr, nullptr, 0, 0, p_ctx, DM, DKH,
                                                   SEQ, DKH, SEQ, 1.f, 0);

    // 7) mha = ctx @ Wo + bo
    mma_gemm<128, 128, 0><<<dim3(8, 16, 1), blk>>>(p_ctx, DM, 0, Wo, DM, 0, bo,
                                                   nullptr, 0, 0, p_mha, DM, 0,
                                                   SEQ, DM, DM, 1.f, 0);
    // 8) part1 = x + mha @ W2 + b2
    mma_gemm<128, 128, 0><<<dim3(8, 16, 1), blk>>>(p_mha, DM, 0, W2, DM, 0, b2,
                                                   x, DM, 0, p_part1, DM, 0,
                                                   SEQ, DM, DM, 1.f, 0);
    // 9) norm2 = LN(part1)
    ln_kernel<<<SEQ, 256>>>(p_part1, g2, beta2, p_norm2);

    // 10) ffh = relu(norm2 @ Wf1 + bf1)
    mma_gemm<128, 128, 0><<<dim3(32, 16, 1), blk>>>(p_norm2, DM, 0, Wf1, DFF, 0, bf1,
                                                    nullptr, 0, 0, p_ffh, DFF, 0,
                                                    SEQ, DFF, DM, 1.f, 1);
    // 11) out = norm2 + ffh @ Wf2 + bf2
    mma_gemm<128, 128, 0><<<dim3(8, 16, 1), blk>>>(p_ffh, DFF, 0, Wf2, DM, 0, bf2,
                                                   p_norm2, DM, 0, out, DM, 0,
                                                   SEQ, DM, DFF, 1.f, 0);
}